// round 12
// baseline (speedup 1.0000x reference)
#include <cuda_runtime.h>
#include <math_constants.h>
#include <stdint.h>

#define BD   4
#define SEQ  2048
#define EMB  1024
#define NH   16
#define HD   64
#define MROWS (BD*SEQ)   // 8192

// Scratch (allocation-free: __device__ globals)
static __device__ float g_q  [(size_t)BD*NH*SEQ*HD];   // (B,H,S,D)
static __device__ float g_k  [(size_t)BD*NH*SEQ*HD];
static __device__ float g_v  [(size_t)BD*NH*SEQ*HD];
static __device__ float g_ctx[(size_t)BD*SEQ*EMB];     // (B,S,E)

__device__ __forceinline__ uint32_t f2tf32(float x) {
    uint32_t r;
    asm("cvt.rna.tf32.f32 %0, %1;" : "=r"(r) : "f"(x));
    return r;
}
__device__ __forceinline__ uint32_t smem_u32(const void* p) {
    uint32_t a;
    asm("{ .reg .u64 t; cvta.to.shared.u64 t, %1; cvt.u32.u64 %0, t; }"
        : "=r"(a) : "l"(p));
    return a;
}
__device__ __forceinline__ void cp_async16(uint32_t saddr, const void* gaddr) {
    asm volatile("cp.async.cg.shared.global [%0], [%1], 16;"
                 :: "r"(saddr), "l"(gaddr) : "memory");
}
// D = A(16x8, row) * B(8x8, col) + D, tf32 inputs, f32 accum. sm_80+ PTX.
// Fragment map: a0=A[g][q] a1=A[g+8][q] a2=A[g][q+4] a3=A[g+8][q+4];
// b0=B[q][g] b1=B[q+4][g]; c0=C[g][2q] c1=C[g][2q+1] c2=C[g+8][2q] c3=C[g+8][2q+1]
__device__ __forceinline__ void mma_tf32(float* c, const uint32_t* a, const uint32_t* b) {
    asm volatile(
        "mma.sync.aligned.m16n8k8.row.col.f32.tf32.tf32.f32 "
        "{%0,%1,%2,%3}, {%4,%5,%6,%7}, {%8,%9}, {%0,%1,%2,%3};\n"
        : "+f"(c[0]), "+f"(c[1]), "+f"(c[2]), "+f"(c[3])
        : "r"(a[0]), "r"(a[1]), "r"(a[2]), "r"(a[3]), "r"(b[0]), "r"(b[1]));
}

// ===========================================================================
// tf32 mma.sync GEMM, cp.async 3-stage pipeline.
// CTA 128x128, 128 thr = 4 warps, warp tile 64x64 (4m x 8n m16n8 tiles).
// smem: fp32 tiles [row][k] stride 12 (BK=8 + pad4) -> fragment LDS banks
// (12g+q) mod 32 all-distinct (conflict-free). cvt.rna at fragment load.
// Stage s = chunk%3; write slot (c+2)%3 == (c-1)%3 protected by the barrier.
// FUSED=1: blockIdx.z selects (A,C,bias); head-split out. FUSED=0: row-major.
// ===========================================================================
#define ST  12            // smem row stride in words (8 k + 4 pad)
#define STGW (128 * ST)   // words per stage per matrix (1536)

template <int FUSED>
__global__ void __launch_bounds__(128, 2) gemm_tf32_mma(
    const float* __restrict__ A0, const float* __restrict__ A1,
    const float* __restrict__ A2,
    const float* __restrict__ W0, const float* __restrict__ W1,
    const float* __restrict__ W2,
    const float* __restrict__ b0, const float* __restrict__ b1,
    const float* __restrict__ b2,
    float* __restrict__ C0, float* __restrict__ C1, float* __restrict__ C2)
{
    __shared__ float sA[3][STGW];   // 18 KB
    __shared__ float sB[3][STGW];   // 18 KB

    const int z = FUSED ? blockIdx.z : 0;
    const float* A    = (z == 0) ? A0 : (z == 1) ? A1 : A2;
    const float* Bw   = (z == 0) ? W0 : (z == 1) ? W1 : W2;
    const float* bias = (z == 0) ? b0 : (z == 1) ? b1 : b2;
    float*       C    = (z == 0) ? C0 : (z == 1) ? C1 : C2;

    const int t  = threadIdx.x;       // 0..127
    const int bm = blockIdx.y * 128;
    const int bn = blockIdx.x * 128;

    const int wid = t >> 5, lane = t & 31;
    const int q = lane & 3, g = lane >> 2;
    const int wm = (wid & 1) * 64;
    const int wn = (wid >> 1) * 64;

    // staging: thread t owns A row (bm+t) and B row (bn+t), 2x16B per chunk
    const float* Ag = A  + (size_t)(bm + t) * EMB;
    const float* Bg = Bw + (size_t)(bn + t) * EMB;
    const uint32_t saw = smem_u32(&sA[0][t * ST]);
    const uint32_t sbw = smem_u32(&sB[0][t * ST]);
    const uint32_t stgBytes = STGW * 4;

    auto issue = [&](int chunk) {
        const int s = chunk - (chunk / 3) * 3;
        const int k0 = chunk * 8;
        cp_async16(saw + s * stgBytes,      Ag + k0);
        cp_async16(saw + s * stgBytes + 16, Ag + k0 + 4);
        cp_async16(sbw + s * stgBytes,      Bg + k0);
        cp_async16(sbw + s * stgBytes + 16, Bg + k0 + 4);
        asm volatile("cp.async.commit_group;" ::: "memory");
    };

    issue(0);
    issue(1);

    float acc[4][8][4] = {};

    for (int c = 0; c < EMB / 8; ++c) {
        if (c < EMB / 8 - 2)
            asm volatile("cp.async.wait_group 1;" ::: "memory");
        else
            asm volatile("cp.async.wait_group 0;" ::: "memory");
        __syncthreads();
        if (c + 2 < EMB / 8) issue(c + 2);

        const int s = c - (c / 3) * 3;
        const float* pa = sA[s];
        const float* pb = sB[s];

        uint32_t af[4][4], bf[8][2];
        #pragma unroll
        for (int tm = 0; tm < 4; ++tm) {
            const int r = wm + tm * 16 + g;
            af[tm][0] = f2tf32(pa[(r    ) * ST + q    ]);
            af[tm][1] = f2tf32(pa[(r + 8) * ST + q    ]);
            af[tm][2] = f2tf32(pa[(r    ) * ST + q + 4]);
            af[tm][3] = f2tf32(pa[(r + 8) * ST + q + 4]);
        }
        #pragma unroll
        for (int tn = 0; tn < 8; ++tn) {
            const int n = wn + tn * 8 + g;
            bf[tn][0] = f2tf32(pb[n * ST + q    ]);
            bf[tn][1] = f2tf32(pb[n * ST + q + 4]);
        }
        #pragma unroll
        for (int tm = 0; tm < 4; ++tm)
            #pragma unroll
            for (int tn = 0; tn < 8; ++tn)
                mma_tf32(acc[tm][tn], af[tm], bf[tn]);
    }

    // epilogue
    #pragma unroll
    for (int tm = 0; tm < 4; ++tm) {
        const int r0 = bm + wm + tm * 16 + g;
        #pragma unroll
        for (int tn = 0; tn < 8; ++tn) {
            const int n  = bn + wn + tn * 8 + 2 * q;
            const float bx = bias[n], by = bias[n + 1];
            float2 v0 = make_float2(acc[tm][tn][0] + bx, acc[tm][tn][1] + by);
            float2 v1 = make_float2(acc[tm][tn][2] + bx, acc[tm][tn][3] + by);
            if (FUSED == 0) {
                *(float2*)&C[(size_t)r0     * EMB + n] = v0;
                *(float2*)&C[(size_t)(r0+8) * EMB + n] = v1;
            } else {
                const int h_ = n >> 6, d_ = n & (HD - 1);
                {
                    const int b_ = r0 >> 11, s_ = r0 & (SEQ - 1);
                    *(float2*)&C[((((size_t)b_ * NH + h_) * SEQ + s_) << 6) + d_] = v0;
                }
                {
                    const int r1 = r0 + 8;
                    const int b_ = r1 >> 11, s_ = r1 & (SEQ - 1);
                    *(float2*)&C[((((size_t)b_ * NH + h_) * SEQ + s_) << 6) + d_] = v1;
                }
            }
        }
    }
}

// ===========================================================================
// tf32 mma.sync flash attention, causal (unchanged from passing R11 kernel).
// ===========================================================================
#define QT_ROWS 128
#define KT      32

__global__ void __launch_bounds__(256, 2) flash_attn_mma(
    const float* __restrict__ Q, const float* __restrict__ K,
    const float* __restrict__ V, float* __restrict__ ctx)
{
    __shared__ uint32_t sK[KT * 68];        // [key][d]   8704 B
    __shared__ uint32_t sV[KT * 72];        // [key][d]   9216 B
    __shared__ uint32_t sP[QT_ROWS * 36];   // [row][key] 18432 B

    const int t  = threadIdx.x;
    const int qt = (SEQ / QT_ROWS - 1) - blockIdx.x;   // longest first
    const int bh = blockIdx.y;
    const int b_ = bh >> 4, h_ = bh & (NH - 1);

    const int wid = t >> 5, lane = t & 31;
    const int g = lane >> 2, q = lane & 3;
    const int m0 = wid * 16;
    const int qbase = qt * QT_ROWS;
    const int grA = qbase + m0 + g;
    const int grB = grA + 8;

    // preload Q fragments (scaled 0.125, rna-tf32)
    const float* Qb = Q + ((size_t)bh * SEQ + qbase + m0) * HD;
    uint32_t qf[8][4];
    #pragma unroll
    for (int ks = 0; ks < 8; ks++) {
        qf[ks][0] = f2tf32(Qb[(g    ) * HD + ks * 8 + q    ] * 0.125f);
        qf[ks][1] = f2tf32(Qb[(g + 8) * HD + ks * 8 + q    ] * 0.125f);
        qf[ks][2] = f2tf32(Qb[(g    ) * HD + ks * 8 + q + 4] * 0.125f);
        qf[ks][3] = f2tf32(Qb[(g + 8) * HD + ks * 8 + q + 4] * 0.125f);
    }

    const int lkey = t >> 3;
    const int ldc  = (t & 7) * 8;

    float mA = -CUDART_INF_F, mB = -CUDART_INF_F;
    float lA = 0.f, lB = 0.f;
    float o[8][4] = {};

    const int jt_max = 4 * qt + 3;
    for (int jt = 0; jt <= jt_max; jt++) {
        const int jtb = jt * KT;
        const float* Kg = K + ((size_t)bh * SEQ + jtb) * HD;
        const float* Vg = V + ((size_t)bh * SEQ + jtb) * HD;

        __syncthreads();
        {
            float4 k0 = *(const float4*)(Kg + lkey * HD + ldc);
            float4 k1 = *(const float4*)(Kg + lkey * HD + ldc + 4);
            float4 v0 = *(const float4*)(Vg + lkey * HD + ldc);
            float4 v1 = *(const float4*)(Vg + lkey * HD + ldc + 4);
            uint4 ku0 = make_uint4(f2tf32(k0.x), f2tf32(k0.y), f2tf32(k0.z), f2tf32(k0.w));
            uint4 ku1 = make_uint4(f2tf32(k1.x), f2tf32(k1.y), f2tf32(k1.z), f2tf32(k1.w));
            uint4 vu0 = make_uint4(f2tf32(v0.x), f2tf32(v0.y), f2tf32(v0.z), f2tf32(v0.w));
            uint4 vu1 = make_uint4(f2tf32(v1.x), f2tf32(v1.y), f2tf32(v1.z), f2tf32(v1.w));
            *(uint4*)&sK[lkey * 68 + ldc    ] = ku0;
            *(uint4*)&sK[lkey * 68 + ldc + 4] = ku1;
            *(uint4*)&sV[lkey * 72 + ldc    ] = vu0;
            *(uint4*)&sV[lkey * 72 + ldc + 4] = vu1;
        }
        __syncthreads();

        // S = (Q/8) * K^T
        float s_[4][4] = {};
        #pragma unroll
        for (int ks = 0; ks < 8; ks++) {
            #pragma unroll
            for (int tn = 0; tn < 4; tn++) {
                uint32_t bfr[2];
                bfr[0] = sK[(tn * 8 + g) * 68 + ks * 8 + q    ];
                bfr[1] = sK[(tn * 8 + g) * 68 + ks * 8 + q + 4];
                mma_tf32(s_[tn], qf[ks], bfr);
            }
        }

        // causal mask + online softmax
        float nmA = -CUDART_INF_F, nmB = -CUDART_INF_F;
        #pragma unroll
        for (int tn = 0; tn < 4; tn++) {
            const int colb = jtb + tn * 8 + 2 * q;
            if (colb     > grA) s_[tn][0] = -CUDART_INF_F;
            if (colb + 1 > grA) s_[tn][1] = -CUDART_INF_F;
            if (colb     > grB) s_[tn][2] = -CUDART_INF_F;
            if (colb + 1 > grB) s_[tn][3] = -CUDART_INF_F;
            nmA = fmaxf(nmA, fmaxf(s_[tn][0], s_[tn][1]));
            nmB = fmaxf(nmB, fmaxf(s_[tn][2], s_[tn][3]));
        }
        nmA = fmaxf(nmA, __shfl_xor_sync(0xffffffffu, nmA, 1, 4));
        nmA = fmaxf(nmA, __shfl_xor_sync(0xffffffffu, nmA, 2, 4));
        nmB = fmaxf(nmB, __shfl_xor_sync(0xffffffffu, nmB, 1, 4));
        nmB = fmaxf(nmB, __shfl_xor_sync(0xffffffffu, nmB, 2, 4));

        const float mAn = fmaxf(mA, nmA), mBn = fmaxf(mB, nmB);
        const float rA = __expf(mA - mAn), rB = __expf(mB - mBn);
        mA = mAn; mB = mBn;

        float sumA = 0.f, sumB = 0.f;
        float pv[4][4];
        #pragma unroll
        for (int tn = 0; tn < 4; tn++) {
            pv[tn][0] = __expf(s_[tn][0] - mAn);
            pv[tn][1] = __expf(s_[tn][1] - mAn);
            pv[tn][2] = __expf(s_[tn][2] - mBn);
            pv[tn][3] = __expf(s_[tn][3] - mBn);
            sumA += pv[tn][0] + pv[tn][1];
            sumB += pv[tn][2] + pv[tn][3];
        }
        sumA += __shfl_xor_sync(0xffffffffu, sumA, 1, 4);
        sumA += __shfl_xor_sync(0xffffffffu, sumA, 2, 4);
        sumB += __shfl_xor_sync(0xffffffffu, sumB, 1, 4);
        sumB += __shfl_xor_sync(0xffffffffu, sumB, 2, 4);
        lA = lA * rA + sumA;
        lB = lB * rB + sumB;
        #pragma unroll
        for (int tn = 0; tn < 8; tn++) {
            o[tn][0] *= rA; o[tn][1] *= rA;
            o[tn][2] *= rB; o[tn][3] *= rB;
        }

        __syncthreads();
        #pragma unroll
        for (int tn = 0; tn < 4; tn++) {
            *(uint2*)&sP[(m0 + g    ) * 36 + tn * 8 + 2 * q] =
                make_uint2(f2tf32(pv[tn][0]), f2tf32(pv[tn][1]));
            *(uint2*)&sP[(m0 + g + 8) * 36 + tn * 8 + 2 * q] =
                make_uint2(f2tf32(pv[tn][2]), f2tf32(pv[tn][3]));
        }
        __syncthreads();

        // O += P * V
        #pragma unroll
        for (int ks = 0; ks < 4; ks++) {
            uint32_t af[4];
            af[0] = sP[(m0 + g    ) * 36 + ks * 8 + q    ];
            af[1] = sP[(m0 + g + 8) * 36 + ks * 8 + q    ];
            af[2] = sP[(m0 + g    ) * 36 + ks * 8 + q + 4];
            af[3] = sP[(m0 + g + 8) * 36 + ks * 8 + q + 4];
            #pragma unroll
            for (int tn = 0; tn < 8; tn++) {
                uint32_t bfr[2];
                bfr[0] = sV[(ks * 8 + q    ) * 72 + tn * 8 + g];
                bfr[1] = sV[(ks * 8 + q + 4) * 72 + tn * 8 + g];
                mma_tf32(o[tn], af, bfr);
            }
        }
    }

    // epilogue: normalize, write ctx (B,S,E)
    const float iA = 1.f / lA, iB = 1.f / lB;
    float* ctxA = ctx + ((size_t)b_ * SEQ + grA) * EMB + h_ * HD;
    float* ctxB = ctx + ((size_t)b_ * SEQ + grB) * EMB + h_ * HD;
    #pragma unroll
    for (int tn = 0; tn < 8; tn++) {
        const int d0 = tn * 8 + 2 * q;
        *(float2*)(ctxA + d0) = make_float2(o[tn][0] * iA, o[tn][1] * iA);
        *(float2*)(ctxB + d0) = make_float2(o[tn][2] * iB, o[tn][3] * iB);
    }
}

// ---------------------------------------------------------------------------
extern "C" void kernel_launch(void* const* d_in, const int* in_sizes, int n_in,
                              void* d_out, int out_size)
{
    (void)in_sizes; (void)n_in; (void)out_size;
    const float* query = (const float*)d_in[0];
    const float* key   = (const float*)d_in[1];
    const float* value = (const float*)d_in[2];
    // d_in[3] = attn_mask (causal triu) — baked into the flash kernel
    const float* q_w = (const float*)d_in[4];
    const float* q_b = (const float*)d_in[5];
    const float* k_w = (const float*)d_in[6];
    const float* k_b = (const float*)d_in[7];
    const float* v_w = (const float*)d_in[8];
    const float* v_b = (const float*)d_in[9];
    const float* o_w = (const float*)d_in[10];
    const float* o_b = (const float*)d_in[11];

    float *gq, *gk, *gv, *gctx;
    cudaGetSymbolAddress((void**)&gq,   g_q);
    cudaGetSymbolAddress((void**)&gk,   g_k);
    cudaGetSymbolAddress((void**)&gv,   g_v);
    cudaGetSymbolAddress((void**)&gctx, g_ctx);

    // fused Q/K/V projections: one launch, 3x grid depth
    gemm_tf32_mma<1><<<dim3(EMB / 128, MROWS / 128, 3), 128>>>(
        query, key, value,
        q_w, k_w, v_w,
        q_b, k_b, v_b,
        gq, gk, gv);

    flash_attn_mma<<<dim3(SEQ / QT_ROWS, BD * NH), 256>>>(gq, gk, gv, gctx);

    gemm_tf32_mma<0><<<dim3(EMB / 128, MROWS / 128, 1), 128>>>(
        gctx, nullptr, nullptr,
        o_w, nullptr, nullptr,
        o_b, nullptr, nullptr,
        (float*)d_out, nullptr, nullptr);
}

// round 16
// speedup vs baseline: 1.1636x; 1.1636x over previous
#include <cuda_runtime.h>
#include <math_constants.h>
#include <stdint.h>

#define BD   4
#define SEQ  2048
#define EMB  1024
#define NH   16
#define HD   64
#define MROWS (BD*SEQ)   // 8192

// Scratch (allocation-free: __device__ globals)
static __device__ float g_q  [(size_t)BD*NH*SEQ*HD];   // (B,H,S,D)
static __device__ float g_k  [(size_t)BD*NH*SEQ*HD];
static __device__ float g_v  [(size_t)BD*NH*SEQ*HD];
static __device__ float g_ctx[(size_t)BD*SEQ*EMB];     // (B,S,E)

__device__ __forceinline__ uint32_t f2tf32(float x) {
    uint32_t r;
    asm("cvt.rna.tf32.f32 %0, %1;" : "=r"(r) : "f"(x));
    return r;
}
__device__ __forceinline__ uint32_t smem_u32(const void* p) {
    uint32_t a;
    asm("{ .reg .u64 t; cvta.to.shared.u64 t, %1; cvt.u32.u64 %0, t; }"
        : "=r"(a) : "l"(p));
    return a;
}
__device__ __forceinline__ void cp_async16(uint32_t saddr, const void* gaddr) {
    asm volatile("cp.async.cg.shared.global [%0], [%1], 16;"
                 :: "r"(saddr), "l"(gaddr) : "memory");
}
// D = A(16x8, row) * B(8x8, col) + D, tf32 inputs, f32 accum. sm_80+ PTX.
// Fragment map: a0=A[g][q] a1=A[g+8][q] a2=A[g][q+4] a3=A[g+8][q+4];
// b0=B[q][g] b1=B[q+4][g]; c0=C[g][2q] c1=C[g][2q+1] c2=C[g+8][2q] c3=C[g+8][2q+1]
__device__ __forceinline__ void mma_tf32(float* c, const uint32_t* a, const uint32_t* b) {
    asm volatile(
        "mma.sync.aligned.m16n8k8.row.col.f32.tf32.tf32.f32 "
        "{%0,%1,%2,%3}, {%4,%5,%6,%7}, {%8,%9}, {%0,%1,%2,%3};\n"
        : "+f"(c[0]), "+f"(c[1]), "+f"(c[2]), "+f"(c[3])
        : "r"(a[0]), "r"(a[1]), "r"(a[2]), "r"(a[3]), "r"(b[0]), "r"(b[1]));
}

// ===========================================================================
// tf32 mma.sync GEMM, cp.async 3-stage pipeline, 256 thr (16 warps/SM @occ2).
// CTA 128x128, 8 warps, warp grid 2m x 4n, warp tile 64x32 (R11-proven).
// smem: fp32 tiles [row][k] stride 12 (BK=8 + pad4); fragment LDS banks
// (12g+q) mod 32 all-distinct (validated in silicon by R12). cvt.rna at
// fragment load. acc[4][4][4]=64 regs -> fits 128-reg cap, occ 24%.
// FUSED=1: blockIdx.z selects (A,C,bias); head-split out. FUSED=0: row-major.
// ===========================================================================
#define ST  12            // smem row stride in words (8 k + 4 pad)
#define STGW (128 * ST)   // words per stage per matrix (1536)

template <int FUSED>
__global__ void __launch_bounds__(256, 2) gemm_tf32_mma(
    const float* __restrict__ A0, const float* __restrict__ A1,
    const float* __restrict__ A2,
    const float* __restrict__ W0, const float* __restrict__ W1,
    const float* __restrict__ W2,
    const float* __restrict__ b0, const float* __restrict__ b1,
    const float* __restrict__ b2,
    float* __restrict__ C0, float* __restrict__ C1, float* __restrict__ C2)
{
    __shared__ float sA[3][STGW];   // 18 KB
    __shared__ float sB[3][STGW];   // 18 KB

    const int z = FUSED ? blockIdx.z : 0;
    const float* A    = (z == 0) ? A0 : (z == 1) ? A1 : A2;
    const float* Bw   = (z == 0) ? W0 : (z == 1) ? W1 : W2;
    const float* bias = (z == 0) ? b0 : (z == 1) ? b1 : b2;
    float*       C    = (z == 0) ? C0 : (z == 1) ? C1 : C2;

    const int t  = threadIdx.x;       // 0..255
    const int bm = blockIdx.y * 128;
    const int bn = blockIdx.x * 128;

    const int wid = t >> 5, lane = t & 31;
    const int q = lane & 3, g = lane >> 2;
    const int wm = (wid & 1) * 64;
    const int wn = (wid >> 1) * 32;

    // staging: 2 threads per row, one 16B cp.async per matrix per chunk
    const int srow = t >> 1;
    const int soff = (t & 1) * 4;
    const float* Ag = A  + (size_t)(bm + srow) * EMB + soff;
    const float* Bg = Bw + (size_t)(bn + srow) * EMB + soff;
    const uint32_t saw = smem_u32(&sA[0][srow * ST + soff]);
    const uint32_t sbw = smem_u32(&sB[0][srow * ST + soff]);
    const uint32_t stgBytes = STGW * 4;

    auto issue = [&](int chunk) {
        const int s = chunk - (chunk / 3) * 3;
        const int k0 = chunk * 8;
        cp_async16(saw + s * stgBytes, Ag + k0);
        cp_async16(sbw + s * stgBytes, Bg + k0);
        asm volatile("cp.async.commit_group;" ::: "memory");
    };

    issue(0);
    issue(1);

    float acc[4][4][4] = {};

    for (int c = 0; c < EMB / 8; ++c) {
        if (c < EMB / 8 - 2)
            asm volatile("cp.async.wait_group 1;" ::: "memory");
        else
            asm volatile("cp.async.wait_group 0;" ::: "memory");
        __syncthreads();
        if (c + 2 < EMB / 8) issue(c + 2);

        const int s = c - (c / 3) * 3;
        const float* pa = sA[s];
        const float* pb = sB[s];

        uint32_t af[4][4], bf[4][2];
        #pragma unroll
        for (int tm = 0; tm < 4; ++tm) {
            const int r = wm + tm * 16 + g;
            af[tm][0] = f2tf32(pa[(r    ) * ST + q    ]);
            af[tm][1] = f2tf32(pa[(r + 8) * ST + q    ]);
            af[tm][2] = f2tf32(pa[(r    ) * ST + q + 4]);
            af[tm][3] = f2tf32(pa[(r + 8) * ST + q + 4]);
        }
        #pragma unroll
        for (int tn = 0; tn < 4; ++tn) {
            const int n = wn + tn * 8 + g;
            bf[tn][0] = f2tf32(pb[n * ST + q    ]);
            bf[tn][1] = f2tf32(pb[n * ST + q + 4]);
        }
        #pragma unroll
        for (int tm = 0; tm < 4; ++tm)
            #pragma unroll
            for (int tn = 0; tn < 4; ++tn)
                mma_tf32(acc[tm][tn], af[tm], bf[tn]);
    }

    // epilogue
    #pragma unroll
    for (int tm = 0; tm < 4; ++tm) {
        const int r0 = bm + wm + tm * 16 + g;
        #pragma unroll
        for (int tn = 0; tn < 4; ++tn) {
            const int n  = bn + wn + tn * 8 + 2 * q;
            const float bx = bias[n], by = bias[n + 1];
            float2 v0 = make_float2(acc[tm][tn][0] + bx, acc[tm][tn][1] + by);
            float2 v1 = make_float2(acc[tm][tn][2] + bx, acc[tm][tn][3] + by);
            if (FUSED == 0) {
                *(float2*)&C[(size_t)r0     * EMB + n] = v0;
                *(float2*)&C[(size_t)(r0+8) * EMB + n] = v1;
            } else {
                const int h_ = n >> 6, d_ = n & (HD - 1);
                {
                    const int b_ = r0 >> 11, s_ = r0 & (SEQ - 1);
                    *(float2*)&C[((((size_t)b_ * NH + h_) * SEQ + s_) << 6) + d_] = v0;
                }
                {
                    const int r1 = r0 + 8;
                    const int b_ = r1 >> 11, s_ = r1 & (SEQ - 1);
                    *(float2*)&C[((((size_t)b_ * NH + h_) * SEQ + s_) << 6) + d_] = v1;
                }
            }
        }
    }
}

// ===========================================================================
// tf32 mma.sync flash attention, causal (unchanged from passing R11 kernel).
// ===========================================================================
#define QT_ROWS 128
#define KT      32

__global__ void __launch_bounds__(256, 2) flash_attn_mma(
    const float* __restrict__ Q, const float* __restrict__ K,
    const float* __restrict__ V, float* __restrict__ ctx)
{
    __shared__ uint32_t sK[KT * 68];        // [key][d]   8704 B
    __shared__ uint32_t sV[KT * 72];        // [key][d]   9216 B
    __shared__ uint32_t sP[QT_ROWS * 36];   // [row][key] 18432 B

    const int t  = threadIdx.x;
    const int qt = (SEQ / QT_ROWS - 1) - blockIdx.x;   // longest first
    const int bh = blockIdx.y;
    const int b_ = bh >> 4, h_ = bh & (NH - 1);

    const int wid = t >> 5, lane = t & 31;
    const int g = lane >> 2, q = lane & 3;
    const int m0 = wid * 16;
    const int qbase = qt * QT_ROWS;
    const int grA = qbase + m0 + g;
    const int grB = grA + 8;

    // preload Q fragments (scaled 0.125, rna-tf32)
    const float* Qb = Q + ((size_t)bh * SEQ + qbase + m0) * HD;
    uint32_t qf[8][4];
    #pragma unroll
    for (int ks = 0; ks < 8; ks++) {
        qf[ks][0] = f2tf32(Qb[(g    ) * HD + ks * 8 + q    ] * 0.125f);
        qf[ks][1] = f2tf32(Qb[(g + 8) * HD + ks * 8 + q    ] * 0.125f);
        qf[ks][2] = f2tf32(Qb[(g    ) * HD + ks * 8 + q + 4] * 0.125f);
        qf[ks][3] = f2tf32(Qb[(g + 8) * HD + ks * 8 + q + 4] * 0.125f);
    }

    const int lkey = t >> 3;
    const int ldc  = (t & 7) * 8;

    float mA = -CUDART_INF_F, mB = -CUDART_INF_F;
    float lA = 0.f, lB = 0.f;
    float o[8][4] = {};

    const int jt_max = 4 * qt + 3;
    for (int jt = 0; jt <= jt_max; jt++) {
        const int jtb = jt * KT;
        const float* Kg = K + ((size_t)bh * SEQ + jtb) * HD;
        const float* Vg = V + ((size_t)bh * SEQ + jtb) * HD;

        __syncthreads();
        {
            float4 k0 = *(const float4*)(Kg + lkey * HD + ldc);
            float4 k1 = *(const float4*)(Kg + lkey * HD + ldc + 4);
            float4 v0 = *(const float4*)(Vg + lkey * HD + ldc);
            float4 v1 = *(const float4*)(Vg + lkey * HD + ldc + 4);
            uint4 ku0 = make_uint4(f2tf32(k0.x), f2tf32(k0.y), f2tf32(k0.z), f2tf32(k0.w));
            uint4 ku1 = make_uint4(f2tf32(k1.x), f2tf32(k1.y), f2tf32(k1.z), f2tf32(k1.w));
            uint4 vu0 = make_uint4(f2tf32(v0.x), f2tf32(v0.y), f2tf32(v0.z), f2tf32(v0.w));
            uint4 vu1 = make_uint4(f2tf32(v1.x), f2tf32(v1.y), f2tf32(v1.z), f2tf32(v1.w));
            *(uint4*)&sK[lkey * 68 + ldc    ] = ku0;
            *(uint4*)&sK[lkey * 68 + ldc + 4] = ku1;
            *(uint4*)&sV[lkey * 72 + ldc    ] = vu0;
            *(uint4*)&sV[lkey * 72 + ldc + 4] = vu1;
        }
        __syncthreads();

        // S = (Q/8) * K^T
        float s_[4][4] = {};
        #pragma unroll
        for (int ks = 0; ks < 8; ks++) {
            #pragma unroll
            for (int tn = 0; tn < 4; tn++) {
                uint32_t bfr[2];
                bfr[0] = sK[(tn * 8 + g) * 68 + ks * 8 + q    ];
                bfr[1] = sK[(tn * 8 + g) * 68 + ks * 8 + q + 4];
                mma_tf32(s_[tn], qf[ks], bfr);
            }
        }

        // causal mask + online softmax
        float nmA = -CUDART_INF_F, nmB = -CUDART_INF_F;
        #pragma unroll
        for (int tn = 0; tn < 4; tn++) {
            const int colb = jtb + tn * 8 + 2 * q;
            if (colb     > grA) s_[tn][0] = -CUDART_INF_F;
            if (colb + 1 > grA) s_[tn][1] = -CUDART_INF_F;
            if (colb     > grB) s_[tn][2] = -CUDART_INF_F;
            if (colb + 1 > grB) s_[tn][3] = -CUDART_INF_F;
            nmA = fmaxf(nmA, fmaxf(s_[tn][0], s_[tn][1]));
            nmB = fmaxf(nmB, fmaxf(s_[tn][2], s_[tn][3]));
        }
        nmA = fmaxf(nmA, __shfl_xor_sync(0xffffffffu, nmA, 1, 4));
        nmA = fmaxf(nmA, __shfl_xor_sync(0xffffffffu, nmA, 2, 4));
        nmB = fmaxf(nmB, __shfl_xor_sync(0xffffffffu, nmB, 1, 4));
        nmB = fmaxf(nmB, __shfl_xor_sync(0xffffffffu, nmB, 2, 4));

        const float mAn = fmaxf(mA, nmA), mBn = fmaxf(mB, nmB);
        const float rA = __expf(mA - mAn), rB = __expf(mB - mBn);
        mA = mAn; mB = mBn;

        float sumA = 0.f, sumB = 0.f;
        float pv[4][4];
        #pragma unroll
        for (int tn = 0; tn < 4; tn++) {
            pv[tn][0] = __expf(s_[tn][0] - mAn);
            pv[tn][1] = __expf(s_[tn][1] - mAn);
            pv[tn][2] = __expf(s_[tn][2] - mBn);
            pv[tn][3] = __expf(s_[tn][3] - mBn);
            sumA += pv[tn][0] + pv[tn][1];
            sumB += pv[tn][2] + pv[tn][3];
        }
        sumA += __shfl_xor_sync(0xffffffffu, sumA, 1, 4);
        sumA += __shfl_xor_sync(0xffffffffu, sumA, 2, 4);
        sumB += __shfl_xor_sync(0xffffffffu, sumB, 1, 4);
        sumB += __shfl_xor_sync(0xffffffffu, sumB, 2, 4);
        lA = lA * rA + sumA;
        lB = lB * rB + sumB;
        #pragma unroll
        for (int tn = 0; tn < 8; tn++) {
            o[tn][0] *= rA; o[tn][1] *= rA;
            o[tn][2] *= rB; o[tn][3] *= rB;
        }

        __syncthreads();
        #pragma unroll
        for (int tn = 0; tn < 4; tn++) {
            *(uint2*)&sP[(m0 + g    ) * 36 + tn * 8 + 2 * q] =
                make_uint2(f2tf32(pv[tn][0]), f2tf32(pv[tn][1]));
            *(uint2*)&sP[(m0 + g + 8) * 36 + tn * 8 + 2 * q] =
                make_uint2(f2tf32(pv[tn][2]), f2tf32(pv[tn][3]));
        }
        __syncthreads();

        // O += P * V
        #pragma unroll
        for (int ks = 0; ks < 4; ks++) {
            uint32_t af[4];
            af[0] = sP[(m0 + g    ) * 36 + ks * 8 + q    ];
            af[1] = sP[(m0 + g + 8) * 36 + ks * 8 + q    ];
            af[2] = sP[(m0 + g    ) * 36 + ks * 8 + q + 4];
            af[3] = sP[(m0 + g + 8) * 36 + ks * 8 + q + 4];
            #pragma unroll
            for (int tn = 0; tn < 8; tn++) {
                uint32_t bfr[2];
                bfr[0] = sV[(ks * 8 + q    ) * 72 + tn * 8 + g];
                bfr[1] = sV[(ks * 8 + q + 4) * 72 + tn * 8 + g];
                mma_tf32(o[tn], af, bfr);
            }
        }
    }

    // epilogue: normalize, write ctx (B,S,E)
    const float iA = 1.f / lA, iB = 1.f / lB;
    float* ctxA = ctx + ((size_t)b_ * SEQ + grA) * EMB + h_ * HD;
    float* ctxB = ctx + ((size_t)b_ * SEQ + grB) * EMB + h_ * HD;
    #pragma unroll
    for (int tn = 0; tn < 8; tn++) {
        const int d0 = tn * 8 + 2 * q;
        *(float2*)(ctxA + d0) = make_float2(o[tn][0] * iA, o[tn][1] * iA);
        *(float2*)(ctxB + d0) = make_float2(o[tn][2] * iB, o[tn][3] * iB);
    }
}

// ---------------------------------------------------------------------------
extern "C" void kernel_launch(void* const* d_in, const int* in_sizes, int n_in,
                              void* d_out, int out_size)
{
    (void)in_sizes; (void)n_in; (void)out_size;
    const float* query = (const float*)d_in[0];
    const float* key   = (const float*)d_in[1];
    const float* value = (const float*)d_in[2];
    // d_in[3] = attn_mask (causal triu) — baked into the flash kernel
    const float* q_w = (const float*)d_in[4];
    const float* q_b = (const float*)d_in[5];
    const float* k_w = (const float*)d_in[6];
    const float* k_b = (const float*)d_in[7];
    const float* v_w = (const float*)d_in[8];
    const float* v_b = (const float*)d_in[9];
    const float* o_w = (const float*)d_in[10];
    const float* o_b = (const float*)d_in[11];

    float *gq, *gk, *gv, *gctx;
    cudaGetSymbolAddress((void**)&gq,   g_q);
    cudaGetSymbolAddress((void**)&gk,   g_k);
    cudaGetSymbolAddress((void**)&gv,   g_v);
    cudaGetSymbolAddress((void**)&gctx, g_ctx);

    // fused Q/K/V projections: one launch, 3x grid depth
    gemm_tf32_mma<1><<<dim3(EMB / 128, MROWS / 128, 3), 256>>>(
        query, key, value,
        q_w, k_w, v_w,
        q_b, k_b, v_b,
        gq, gk, gv);

    flash_attn_mma<<<dim3(SEQ / QT_ROWS, BD * NH), 256>>>(gq, gk, gv, gctx);

    gemm_tf32_mma<0><<<dim3(EMB / 128, MROWS / 128, 1), 256>>>(
        gctx, nullptr, nullptr,
        o_w, nullptr, nullptr,
        o_b, nullptr, nullptr,
        (float*)d_out, nullptr, nullptr);
}